// round 6
// baseline (speedup 1.0000x reference)
#include <cuda_runtime.h>
#include <math.h>

// Problem constants (match reference)
#define N_ENT   100000
#define N_USR   50000
#define N_EDGE  1000000
#define C       64
#define N_FACT  4
#define NRELM1  9           // N_REL - 1
#define TEMP    0.2f
#define SCALE_R 0.0883883476483184f   // 1 / (2 * sqrt(32))

// ---------------- device scratch (no allocation allowed) ----------------
__device__ float g_score_r[N_EDGE];
__device__ float g_score_trip[N_EDGE];
__device__ float g_kg_mask[N_EDGE];
__device__ float g_sumexp_r[N_ENT];
__device__ float g_sumexp_t[N_ENT];
__device__ float g_counts[N_ENT];
__device__ float g_ent[N_ENT * C];       // current entity embedding
__device__ float g_usr[N_USR * C];       // current user embedding
__device__ float g_ent_agg[N_ENT * C];
__device__ float g_u_agg[N_USR * C];
__device__ float g_u_rel[NRELM1 * C];    // (W W^T) w_t
__device__ float g_wnorm2[NRELM1];
__device__ float g_disen_w[N_FACT * C];  // softmax(disen_att) @ weight

__device__ __forceinline__ float warp_sum(float v) {
#pragma unroll
    for (int o = 16; o; o >>= 1) v += __shfl_xor_sync(0xffffffffu, v, o);
    return v;
}

// ---------------- tiny dense precompute + cor ----------------
__global__ void k_prep(const float* __restrict__ W,      // kg_W_r [64,64]
                       const float* __restrict__ weight, // [9,64]
                       const float* __restrict__ A,      // disen_weight_att [4,9]
                       float* __restrict__ cor_out) {
    __shared__ float G[64 * 64];
    __shared__ float sm[N_FACT][NRELM1];
    int tid = threadIdx.x;

    // G = W W^T
    for (int idx = tid; idx < 64 * 64; idx += blockDim.x) {
        int i = idx >> 6, j = idx & 63;
        float s = 0.f;
#pragma unroll 8
        for (int c = 0; c < 64; c++) s += W[i * 64 + c] * W[j * 64 + c];
        G[idx] = s;
    }
    __syncthreads();

    // u_t = G @ w_t
    for (int idx = tid; idx < NRELM1 * C; idx += blockDim.x) {
        int t = idx / C, i = idx % C;
        float s = 0.f;
#pragma unroll 8
        for (int j = 0; j < 64; j++) s += G[i * 64 + j] * weight[t * 64 + j];
        g_u_rel[idx] = s;
    }
    if (tid < NRELM1) {
        float s = 0.f;
        for (int c = 0; c < 64; c++) { float v = weight[tid * 64 + c]; s += v * v; }
        g_wnorm2[tid] = s;
    }
    if (tid < N_FACT) {
        float m = -1e30f;
        for (int j = 0; j < NRELM1; j++) m = fmaxf(m, A[tid * NRELM1 + j]);
        float s = 0.f;
        for (int j = 0; j < NRELM1; j++) { float e = expf(A[tid * NRELM1 + j] - m); sm[tid][j] = e; s += e; }
        for (int j = 0; j < NRELM1; j++) sm[tid][j] /= s;
    }
    __syncthreads();

    // disen_w = softmax(A) @ weight
    for (int idx = tid; idx < N_FACT * C; idx += blockDim.x) {
        int f = idx / C, c = idx % C;
        float s = 0.f;
        for (int j = 0; j < NRELM1; j++) s += sm[f][j] * weight[j * 64 + c];
        g_disen_w[idx] = s;
    }

    // cor = sum_i (ttl_i - pos_i) / TEMP
    if (tid == 0) {
        float cor = 0.f;
        for (int i = 0; i < NRELM1; i++) {
            float n2 = 0.f;
            for (int f = 0; f < N_FACT; f++) { float v = A[f * NRELM1 + i]; n2 += v * v; }
            float nrm = sqrtf(n2);
            float pos = 0.f;
            for (int f = 0; f < N_FACT; f++) { float v = A[f * NRELM1 + i] / nrm; pos += v * v; }
            float ttl = 0.f;
            for (int j = 0; j < NRELM1; j++) {
                float d = 0.f;
                for (int f = 0; f < N_FACT; f++) d += A[f * NRELM1 + i] * A[f * NRELM1 + j];
                ttl += d;
            }
            cor += (ttl - pos) / TEMP;
        }
        *cor_out = cor;
    }
}

// ---------------- init: copy embeddings to state + output, zero segment arrays ----------------
__global__ void k_init(const float* __restrict__ eemb, const float* __restrict__ uemb,
                       float* __restrict__ out_ent, float* __restrict__ out_usr) {
    const int NE4 = N_ENT * C / 4, NU4 = N_USR * C / 4;
    int i = blockIdx.x * blockDim.x + threadIdx.x;
    if (i < NE4) {
        float4 v = ((const float4*)eemb)[i];
        ((float4*)g_ent)[i] = v;
        ((float4*)out_ent)[i] = v;
    } else if (i < NE4 + NU4) {
        int j = i - NE4;
        float4 v = ((const float4*)uemb)[j];
        ((float4*)g_usr)[j] = v;
        ((float4*)out_usr)[j] = v;
    }
}

__global__ void k_zero_seg() {
    int i = blockIdx.x * blockDim.x + threadIdx.x;
    if (i < N_ENT) { g_sumexp_r[i] = 0.f; g_sumexp_t[i] = 0.f; g_counts[i] = 0.f; }
}

__global__ void k_zero_agg() {
    const int NE4 = N_ENT * C / 4, NU4 = N_USR * C / 4;
    int i = blockIdx.x * blockDim.x + threadIdx.x;
    if (i < NE4) ((float4*)g_ent_agg)[i] = make_float4(0.f, 0.f, 0.f, 0.f);
    else if (i < NE4 + NU4) ((float4*)g_u_agg)[i - NE4] = make_float4(0.f, 0.f, 0.f, 0.f);
}

// ---------------- edge pass 1: score_r, sum exp, counts ----------------
__global__ void kE1(const float* __restrict__ ent, const int* __restrict__ head,
                    const int* __restrict__ et) {
    __shared__ float s_u[NRELM1 * C];
    for (int i = threadIdx.x; i < NRELM1 * C; i += blockDim.x) s_u[i] = g_u_rel[i];
    __syncthreads();
    int gt = blockIdx.x * blockDim.x + threadIdx.x;
    int w = gt >> 5, lane = gt & 31;
    if (w >= N_EDGE) return;
    int h = head[w], t = et[w] - 1;
    float2 hv = *(const float2*)(ent + (size_t)h * C + lane * 2);
    float2 uv = *(const float2*)(s_u + t * C + lane * 2);
    float dot = warp_sum(hv.x * uv.x + hv.y * uv.y);
    if (lane == 0) {
        float sc = dot * SCALE_R;
        g_score_r[w] = sc;
        atomicAdd(&g_sumexp_r[h], expf(sc));
        atomicAdd(&g_counts[h], 1.0f);
    }
}

// ---------------- edge pass 2: score_trip, sum exp ----------------
__global__ void kE2(const float* __restrict__ ent, const int* __restrict__ head,
                    const int* __restrict__ tail, const int* __restrict__ et) {
    int gt = blockIdx.x * blockDim.x + threadIdx.x;
    int w = gt >> 5, lane = gt & 31;
    if (w >= N_EDGE) return;
    int h = head[w], tl = tail[w], t = et[w] - 1;
    float2 hv = *(const float2*)(ent + (size_t)h * C + lane * 2);
    float2 tv = *(const float2*)(ent + (size_t)tl * C + lane * 2);
    float dot = warp_sum(hv.x * tv.x + hv.y * tv.y);
    if (lane == 0) {
        float rs = expf(g_score_r[w]) / (g_sumexp_r[h] + 1e-16f);
        float st = dot + rs * rs * g_wnorm2[t];
        g_score_trip[w] = st;
        atomicAdd(&g_sumexp_t[h], expf(st));
    }
}

// ---------------- edge pass 3: kg_mask ----------------
__global__ void kE3(const int* __restrict__ head) {
    int i = blockIdx.x * blockDim.x + threadIdx.x;
    if (i < N_EDGE)
        g_kg_mask[i] = expf(g_score_trip[i]) / (g_sumexp_t[head[i]] + 1e-16f);
}

// ---------------- hop: KG aggregation (scatter into ent_agg) ----------------
__global__ void kH2(const int* __restrict__ head, const int* __restrict__ tail,
                    const int* __restrict__ et, const float* __restrict__ weight) {
    __shared__ float s_w[NRELM1 * C];
    for (int i = threadIdx.x; i < NRELM1 * C; i += blockDim.x) s_w[i] = weight[i];
    __syncthreads();
    int gt = blockIdx.x * blockDim.x + threadIdx.x;
    int w = gt >> 5, lane = gt & 31;
    if (w >= N_EDGE) return;
    int h = head[w], tl = tail[w], t = et[w] - 1;
    float m = g_kg_mask[w];
    float2 ev = *(const float2*)(g_ent + (size_t)tl * C + lane * 2);
    float2 wv = *(const float2*)(s_w + t * C + lane * 2);
    float2 r = make_float2(ev.x * wv.x * m, ev.y * wv.y * m);
    atomicAdd((float2*)(g_ent_agg + (size_t)h * C + lane * 2), r);
}

// ---------------- hop: UI aggregation (scatter into u_agg) ----------------
__global__ void kH3(const int* __restrict__ rows, const int* __restrict__ cols,
                    const float* __restrict__ vals) {
    int gt = blockIdx.x * blockDim.x + threadIdx.x;
    int w = gt >> 5, lane = gt & 31;
    if (w >= N_EDGE) return;
    int u = rows[w], ce = cols[w];
    float v = vals[w];
    float2 ev = *(const float2*)(g_ent + (size_t)ce * C + lane * 2);
    float2 r = make_float2(ev.x * v, ev.y * v);
    atomicAdd((float2*)(g_u_agg + (size_t)u * C + lane * 2), r);
}

// ---------------- hop: entity update (mean -> l2norm -> residual) ----------------
__global__ void kH4(float* __restrict__ out_ent) {
    int gt = blockIdx.x * blockDim.x + threadIdx.x;
    int n = gt >> 5, lane = gt & 31;
    if (n >= N_ENT) return;
    float cnt = fmaxf(g_counts[n], 1.0f);
    float2 a = *(const float2*)(g_ent_agg + (size_t)n * C + lane * 2);
    a.x /= cnt; a.y /= cnt;
    float ss = warp_sum(a.x * a.x + a.y * a.y);
    float inv = 1.0f / fmaxf(sqrtf(ss), 1e-12f);
    float2 e2 = make_float2(a.x * inv, a.y * inv);
    *(float2*)(g_ent + (size_t)n * C + lane * 2) = e2;
    float2* o = (float2*)(out_ent + (size_t)n * C + lane * 2);
    float2 cur = *o; cur.x += e2.x; cur.y += e2.y; *o = cur;
}

// ---------------- hop: user update (factor attention -> mix -> l2norm -> residual) --------
__global__ void kH5(const float* __restrict__ latent, float* __restrict__ out_usr) {
    __shared__ float s_lat[N_FACT * C];
    __shared__ float s_dw[N_FACT * C];
    for (int i = threadIdx.x; i < N_FACT * C; i += blockDim.x) {
        s_lat[i] = latent[i];
        s_dw[i] = g_disen_w[i];
    }
    __syncthreads();
    int gt = blockIdx.x * blockDim.x + threadIdx.x;
    int u = gt >> 5, lane = gt & 31;
    if (u >= N_USR) return;
    float2 uv = *(const float2*)(g_usr + (size_t)u * C + lane * 2);
    float d[N_FACT];
#pragma unroll
    for (int f = 0; f < N_FACT; f++) {
        float2 lv = *(const float2*)(s_lat + f * C + lane * 2);
        d[f] = uv.x * lv.x + uv.y * lv.y;
    }
#pragma unroll
    for (int o = 16; o; o >>= 1) {
#pragma unroll
        for (int f = 0; f < N_FACT; f++) d[f] += __shfl_xor_sync(0xffffffffu, d[f], o);
    }
    float m = fmaxf(fmaxf(d[0], d[1]), fmaxf(d[2], d[3]));
    float e[N_FACT], s = 0.f;
#pragma unroll
    for (int f = 0; f < N_FACT; f++) { e[f] = expf(d[f] - m); s += e[f]; }
    float2 mix = make_float2(0.f, 0.f);
#pragma unroll
    for (int f = 0; f < N_FACT; f++) {
        float sc = e[f] / s;
        float2 dv = *(const float2*)(s_dw + f * C + lane * 2);
        mix.x += sc * dv.x; mix.y += sc * dv.y;
    }
    float2 ua = *(const float2*)(g_u_agg + (size_t)u * C + lane * 2);
    float2 r = make_float2(ua.x * (1.f + mix.x), ua.y * (1.f + mix.y));
    float ss = warp_sum(r.x * r.x + r.y * r.y);
    float inv = 1.0f / fmaxf(sqrtf(ss), 1e-12f);
    r.x *= inv; r.y *= inv;
    *(float2*)(g_usr + (size_t)u * C + lane * 2) = r;
    float2* o = (float2*)(out_usr + (size_t)u * C + lane * 2);
    float2 cur = *o; cur.x += r.x; cur.y += r.y; *o = cur;
}

// ---------------- launch ----------------
extern "C" void kernel_launch(void* const* d_in, const int* in_sizes, int n_in,
                              void* d_out, int out_size) {
    const float* user_emb   = (const float*)d_in[0];
    const float* entity_emb = (const float*)d_in[1];
    const float* latent_emb = (const float*)d_in[2];
    const float* weight     = (const float*)d_in[3];
    const float* disen      = (const float*)d_in[4];
    const float* kgW        = (const float*)d_in[5];
    const float* ui_vals    = (const float*)d_in[6];
    const int*   edge_index = (const int*)d_in[7];
    const int*   edge_type  = (const int*)d_in[8];
    const int*   ui_rows    = (const int*)d_in[9];
    const int*   ui_cols    = (const int*)d_in[10];

    float* out     = (float*)d_out;
    float* out_ent = out;
    float* out_usr = out + (size_t)N_ENT * C;
    float* out_cor = out + (size_t)N_ENT * C + (size_t)N_USR * C;

    const int* head = edge_index;
    const int* tail = edge_index + N_EDGE;

    k_prep<<<1, 256>>>(kgW, weight, disen, out_cor);

    int nInit = (N_ENT * C / 4 + N_USR * C / 4 + 255) / 256;
    k_init<<<nInit, 256>>>(entity_emb, user_emb, out_ent, out_usr);
    k_zero_seg<<<(N_ENT + 255) / 256, 256>>>();

    dim3 eg((unsigned)(((long long)N_EDGE * 32 + 255) / 256));
    kE1<<<eg, 256>>>(entity_emb, head, edge_type);
    kE2<<<eg, 256>>>(entity_emb, head, tail, edge_type);
    kE3<<<(N_EDGE + 255) / 256, 256>>>(head);

    for (int hop = 0; hop < 2; hop++) {
        k_zero_agg<<<nInit, 256>>>();
        kH2<<<eg, 256>>>(head, tail, edge_type, weight);
        kH3<<<eg, 256>>>(ui_rows, ui_cols, ui_vals);
        kH4<<<(unsigned)(((long long)N_ENT * 32 + 255) / 256), 256>>>(out_ent);
        kH5<<<(unsigned)(((long long)N_USR * 32 + 255) / 256), 256>>>(latent_emb, out_usr);
    }
}

// round 8
// speedup vs baseline: 1.9407x; 1.9407x over previous
#include <cuda_runtime.h>
#include <math.h>

// Problem constants (match reference)
#define N_ENT   100000
#define N_USR   50000
#define N_EDGE  1000000
#define C       64
#define N_FACT  4
#define NRELM1  9           // N_REL - 1
#define TEMP    0.2f
#define SCALE_R 0.0883883476483184f   // 1 / (2 * sqrt(32))

// ---------------- device scratch (no allocation allowed) ----------------
__device__ __align__(16) float g_score_r[N_EDGE];     // holds exp(score_r) after kE12
__device__ __align__(16) float g_score_trip[N_EDGE];  // raw dot(h,t) -> exp(score_trip)
__device__ __align__(16) float g_kg_mask[N_EDGE];
__device__ __align__(16) float g_sumexp_r[N_ENT];
__device__ __align__(16) float g_sumexp_t[N_ENT];
__device__ __align__(16) float g_counts[N_ENT];
__device__ __align__(16) float g_ent[N_ENT * C];      // current entity embedding
__device__ __align__(16) float g_usr[N_USR * C];      // current user embedding
__device__ __align__(16) float g_ent_agg[N_ENT * C];
__device__ __align__(16) float g_u_agg[N_USR * C];
__device__ __align__(16) float g_u_rel[NRELM1 * C];   // (W W^T) w_t
__device__ __align__(16) float g_wnorm2[NRELM1];
__device__ __align__(16) float g_disen_w[N_FACT * C]; // softmax(disen_att) @ weight

__device__ __forceinline__ float dot4(float4 a, float4 b) {
    return a.x * b.x + a.y * b.y + a.z * b.z + a.w * b.w;
}

// fire-and-forget 128-bit vector reduction (sm_90+)
__device__ __forceinline__ void red_add_v4(float* addr, float4 v) {
    asm volatile("red.global.add.v4.f32 [%0], {%1,%2,%3,%4};"
                 :: "l"(addr), "f"(v.x), "f"(v.y), "f"(v.z), "f"(v.w)
                 : "memory");
}

// ---------------- tiny dense precompute + cor ----------------
__global__ void k_prep(const float* __restrict__ W,      // kg_W_r [64,64]
                       const float* __restrict__ weight, // [9,64]
                       const float* __restrict__ A,      // disen_weight_att [4,9]
                       float* __restrict__ cor_out) {
    __shared__ float G[64 * 64];
    __shared__ float sm[N_FACT][NRELM1];
    int tid = threadIdx.x;

    // G = W W^T
    for (int idx = tid; idx < 64 * 64; idx += blockDim.x) {
        int i = idx >> 6, j = idx & 63;
        float s = 0.f;
#pragma unroll 8
        for (int c = 0; c < 64; c++) s += W[i * 64 + c] * W[j * 64 + c];
        G[idx] = s;
    }
    __syncthreads();

    // u_t = G @ w_t
    for (int idx = tid; idx < NRELM1 * C; idx += blockDim.x) {
        int t = idx / C, i = idx % C;
        float s = 0.f;
#pragma unroll 8
        for (int j = 0; j < 64; j++) s += G[i * 64 + j] * weight[t * 64 + j];
        g_u_rel[idx] = s;
    }
    if (tid < NRELM1) {
        float s = 0.f;
        for (int c = 0; c < 64; c++) { float v = weight[tid * 64 + c]; s += v * v; }
        g_wnorm2[tid] = s;
    }
    if (tid < N_FACT) {
        float m = -1e30f;
        for (int j = 0; j < NRELM1; j++) m = fmaxf(m, A[tid * NRELM1 + j]);
        float s = 0.f;
        for (int j = 0; j < NRELM1; j++) { float e = expf(A[tid * NRELM1 + j] - m); sm[tid][j] = e; s += e; }
        for (int j = 0; j < NRELM1; j++) sm[tid][j] /= s;
    }
    __syncthreads();

    // disen_w = softmax(A) @ weight
    for (int idx = tid; idx < N_FACT * C; idx += blockDim.x) {
        int f = idx / C, c = idx % C;
        float s = 0.f;
        for (int j = 0; j < NRELM1; j++) s += sm[f][j] * weight[j * 64 + c];
        g_disen_w[idx] = s;
    }

    // cor = sum_i (ttl_i - pos_i) / TEMP
    if (tid == 0) {
        float cor = 0.f;
        for (int i = 0; i < NRELM1; i++) {
            float n2 = 0.f;
            for (int f = 0; f < N_FACT; f++) { float v = A[f * NRELM1 + i]; n2 += v * v; }
            float nrm = sqrtf(n2);
            float pos = 0.f;
            for (int f = 0; f < N_FACT; f++) { float v = A[f * NRELM1 + i] / nrm; pos += v * v; }
            float ttl = 0.f;
            for (int j = 0; j < NRELM1; j++) {
                float d = 0.f;
                for (int f = 0; f < N_FACT; f++) d += A[f * NRELM1 + i] * A[f * NRELM1 + j];
                ttl += d;
            }
            cor += (ttl - pos) / TEMP;
        }
        *cor_out = cor;
    }
}

// ---------------- init: copy embeddings to state + output ----------------
__global__ void k_init(const float* __restrict__ eemb, const float* __restrict__ uemb,
                       float* __restrict__ out_ent, float* __restrict__ out_usr) {
    const int NE4 = N_ENT * C / 4, NU4 = N_USR * C / 4;
    int i = blockIdx.x * blockDim.x + threadIdx.x;
    if (i < NE4) {
        float4 v = ((const float4*)eemb)[i];
        ((float4*)g_ent)[i] = v;
        ((float4*)out_ent)[i] = v;
    } else if (i < NE4 + NU4) {
        int j = i - NE4;
        float4 v = ((const float4*)uemb)[j];
        ((float4*)g_usr)[j] = v;
        ((float4*)out_usr)[j] = v;
    }
}

__global__ void k_zero_seg() {
    int i = blockIdx.x * blockDim.x + threadIdx.x;
    if (i < N_ENT) { g_sumexp_r[i] = 0.f; g_sumexp_t[i] = 0.f; g_counts[i] = 0.f; }
}

__global__ void k_zero_agg() {
    const int NE4 = N_ENT * C / 4, NU4 = N_USR * C / 4;
    int i = blockIdx.x * blockDim.x + threadIdx.x;
    if (i < NE4) ((float4*)g_ent_agg)[i] = make_float4(0.f, 0.f, 0.f, 0.f);
    else if (i < NE4 + NU4) ((float4*)g_u_agg)[i - NE4] = make_float4(0.f, 0.f, 0.f, 0.f);
}

// ---------------- fused edge pass 1: score_r (exp'd) + raw dot(h,t) + segment sums ------
// 8 lanes per edge; each lane owns 8 channels (2 x float4).
__global__ void kE12(const float* __restrict__ ent, const int* __restrict__ head,
                     const int* __restrict__ tail, const int* __restrict__ et) {
    __shared__ __align__(16) float s_u[NRELM1 * C];
    for (int i = threadIdx.x; i < NRELM1 * C; i += blockDim.x) s_u[i] = g_u_rel[i];
    __syncthreads();
    int gt = blockIdx.x * blockDim.x + threadIdx.x;
    int w = gt >> 3, lane = gt & 7;
    if (w >= N_EDGE) return;
    int h = head[w], tl = tail[w], t = et[w] - 1;
    const float4* hp = (const float4*)(ent + (size_t)h * C) + lane * 2;
    const float4* tp = (const float4*)(ent + (size_t)tl * C) + lane * 2;
    const float4* up = (const float4*)(s_u + t * C) + lane * 2;
    float4 h0 = hp[0], h1 = hp[1];
    float4 t0 = tp[0], t1 = tp[1];
    float4 u0 = up[0], u1 = up[1];
    float du = dot4(h0, u0) + dot4(h1, u1);   // h . (W W^T w_t)
    float dt = dot4(h0, t0) + dot4(h1, t1);   // h . t
#pragma unroll
    for (int o = 4; o; o >>= 1) {
        du += __shfl_xor_sync(0xffffffffu, du, o);
        dt += __shfl_xor_sync(0xffffffffu, dt, o);
    }
    if (lane == 0) {
        float e = expf(du * SCALE_R);
        g_score_r[w] = e;          // store exp(score_r)
        g_score_trip[w] = dt;      // raw h.t, finalized in kE2b
        atomicAdd(&g_sumexp_r[h], e);
        atomicAdd(&g_counts[h], 1.0f);
    }
}

// ---------------- edge pass 2: finalize score_trip (scalar per edge) ----------------
__global__ void kE2b(const int* __restrict__ head, const int* __restrict__ et) {
    int i = blockIdx.x * blockDim.x + threadIdx.x;
    if (i >= N_EDGE) return;
    int h = head[i];
    float rs = g_score_r[i] / (g_sumexp_r[h] + 1e-16f);
    float st = g_score_trip[i] + rs * rs * g_wnorm2[et[i] - 1];
    float e = expf(st);
    g_score_trip[i] = e;           // store exp(score_trip)
    atomicAdd(&g_sumexp_t[h], e);
}

// ---------------- edge pass 3: kg_mask ----------------
__global__ void kE3(const int* __restrict__ head) {
    int i = blockIdx.x * blockDim.x + threadIdx.x;
    if (i < N_EDGE)
        g_kg_mask[i] = g_score_trip[i] / (g_sumexp_t[head[i]] + 1e-16f);
}

// ---------------- hop: KG aggregation (8 lanes/edge, red.v4 scatter) ----------------
__global__ void kH2(const int* __restrict__ head, const int* __restrict__ tail,
                    const int* __restrict__ et, const float* __restrict__ weight) {
    __shared__ __align__(16) float s_w[NRELM1 * C];
    for (int i = threadIdx.x; i < NRELM1 * C; i += blockDim.x) s_w[i] = weight[i];
    __syncthreads();
    int gt = blockIdx.x * blockDim.x + threadIdx.x;
    int w = gt >> 3, lane = gt & 7;
    if (w >= N_EDGE) return;
    int h = head[w], tl = tail[w], t = et[w] - 1;
    float m = g_kg_mask[w];
    const float4* ep = (const float4*)(g_ent + (size_t)tl * C) + lane * 2;
    const float4* wp = (const float4*)(s_w + t * C) + lane * 2;
    float4 e0 = ep[0], e1 = ep[1];
    float4 w0 = wp[0], w1 = wp[1];
    float4 r0 = make_float4(e0.x * w0.x * m, e0.y * w0.y * m, e0.z * w0.z * m, e0.w * w0.w * m);
    float4 r1 = make_float4(e1.x * w1.x * m, e1.y * w1.y * m, e1.z * w1.z * m, e1.w * w1.w * m);
    float* dst = g_ent_agg + (size_t)h * C + lane * 8;
    red_add_v4(dst, r0);
    red_add_v4(dst + 4, r1);
}

// ---------------- hop: UI aggregation (8 lanes/edge, red.v4 scatter) ----------------
__global__ void kH3(const int* __restrict__ rows, const int* __restrict__ cols,
                    const float* __restrict__ vals) {
    int gt = blockIdx.x * blockDim.x + threadIdx.x;
    int w = gt >> 3, lane = gt & 7;
    if (w >= N_EDGE) return;
    int u = rows[w], ce = cols[w];
    float v = vals[w];
    const float4* ep = (const float4*)(g_ent + (size_t)ce * C) + lane * 2;
    float4 e0 = ep[0], e1 = ep[1];
    float4 r0 = make_float4(e0.x * v, e0.y * v, e0.z * v, e0.w * v);
    float4 r1 = make_float4(e1.x * v, e1.y * v, e1.z * v, e1.w * v);
    float* dst = g_u_agg + (size_t)u * C + lane * 8;
    red_add_v4(dst, r0);
    red_add_v4(dst + 4, r1);
}

// ---------------- hop: entity update (16 lanes/entity, float4; re-zeroes agg) --------
__global__ void kH4(float* __restrict__ out_ent) {
    int gt = blockIdx.x * blockDim.x + threadIdx.x;
    int n = gt >> 4, lane = gt & 15;
    if (n >= N_ENT) return;
    float inv_cnt = 1.0f / fmaxf(g_counts[n], 1.0f);
    float4* ap = (float4*)(g_ent_agg + (size_t)n * C) + lane;
    float4 a = *ap;
    *ap = make_float4(0.f, 0.f, 0.f, 0.f);   // re-zero for next hop
    a.x *= inv_cnt; a.y *= inv_cnt; a.z *= inv_cnt; a.w *= inv_cnt;
    float ss = dot4(a, a);
#pragma unroll
    for (int o = 8; o; o >>= 1) ss += __shfl_xor_sync(0xffffffffu, ss, o);
    float inv = 1.0f / fmaxf(sqrtf(ss), 1e-12f);
    float4 e2 = make_float4(a.x * inv, a.y * inv, a.z * inv, a.w * inv);
    ((float4*)(g_ent + (size_t)n * C))[lane] = e2;
    float4* o4 = (float4*)(out_ent + (size_t)n * C) + lane;
    float4 cur = *o4;
    cur.x += e2.x; cur.y += e2.y; cur.z += e2.z; cur.w += e2.w;
    *o4 = cur;
}

// ---------------- hop: user update (16 lanes/user, float4; re-zeroes agg) ------------
__global__ void kH5(const float* __restrict__ latent, float* __restrict__ out_usr) {
    __shared__ __align__(16) float s_lat[N_FACT * C];
    __shared__ __align__(16) float s_dw[N_FACT * C];
    for (int i = threadIdx.x; i < N_FACT * C; i += blockDim.x) {
        s_lat[i] = latent[i];
        s_dw[i] = g_disen_w[i];
    }
    __syncthreads();
    int gt = blockIdx.x * blockDim.x + threadIdx.x;
    int u = gt >> 4, lane = gt & 15;
    if (u >= N_USR) return;
    float4 uv = ((const float4*)(g_usr + (size_t)u * C))[lane];
    float d[N_FACT];
#pragma unroll
    for (int f = 0; f < N_FACT; f++)
        d[f] = dot4(uv, ((const float4*)(s_lat + f * C))[lane]);
#pragma unroll
    for (int o = 8; o; o >>= 1) {
#pragma unroll
        for (int f = 0; f < N_FACT; f++) d[f] += __shfl_xor_sync(0xffffffffu, d[f], o);
    }
    float m = fmaxf(fmaxf(d[0], d[1]), fmaxf(d[2], d[3]));
    float e[N_FACT], s = 0.f;
#pragma unroll
    for (int f = 0; f < N_FACT; f++) { e[f] = expf(d[f] - m); s += e[f]; }
    float4 mix = make_float4(0.f, 0.f, 0.f, 0.f);
#pragma unroll
    for (int f = 0; f < N_FACT; f++) {
        float sc = e[f] / s;
        float4 dv = ((const float4*)(s_dw + f * C))[lane];
        mix.x += sc * dv.x; mix.y += sc * dv.y; mix.z += sc * dv.z; mix.w += sc * dv.w;
    }
    float4* uap = (float4*)(g_u_agg + (size_t)u * C) + lane;
    float4 ua = *uap;
    *uap = make_float4(0.f, 0.f, 0.f, 0.f);  // re-zero for next hop
    float4 r = make_float4(ua.x * (1.f + mix.x), ua.y * (1.f + mix.y),
                           ua.z * (1.f + mix.z), ua.w * (1.f + mix.w));
    float ss = dot4(r, r);
#pragma unroll
    for (int o = 8; o; o >>= 1) ss += __shfl_xor_sync(0xffffffffu, ss, o);
    float inv = 1.0f / fmaxf(sqrtf(ss), 1e-12f);
    r.x *= inv; r.y *= inv; r.z *= inv; r.w *= inv;
    ((float4*)(g_usr + (size_t)u * C))[lane] = r;
    float4* o4 = (float4*)(out_usr + (size_t)u * C) + lane;
    float4 cur = *o4;
    cur.x += r.x; cur.y += r.y; cur.z += r.z; cur.w += r.w;
    *o4 = cur;
}

// ---------------- launch ----------------
extern "C" void kernel_launch(void* const* d_in, const int* in_sizes, int n_in,
                              void* d_out, int out_size) {
    const float* user_emb   = (const float*)d_in[0];
    const float* entity_emb = (const float*)d_in[1];
    const float* latent_emb = (const float*)d_in[2];
    const float* weight     = (const float*)d_in[3];
    const float* disen      = (const float*)d_in[4];
    const float* kgW        = (const float*)d_in[5];
    const float* ui_vals    = (const float*)d_in[6];
    const int*   edge_index = (const int*)d_in[7];
    const int*   edge_type  = (const int*)d_in[8];
    const int*   ui_rows    = (const int*)d_in[9];
    const int*   ui_cols    = (const int*)d_in[10];

    float* out     = (float*)d_out;
    float* out_ent = out;
    float* out_usr = out + (size_t)N_ENT * C;
    float* out_cor = out + (size_t)N_ENT * C + (size_t)N_USR * C;

    const int* head = edge_index;
    const int* tail = edge_index + N_EDGE;

    k_prep<<<1, 256>>>(kgW, weight, disen, out_cor);

    int nInit = (N_ENT * C / 4 + N_USR * C / 4 + 255) / 256;
    k_init<<<nInit, 256>>>(entity_emb, user_emb, out_ent, out_usr);
    k_zero_seg<<<(N_ENT + 255) / 256, 256>>>();
    k_zero_agg<<<nInit, 256>>>();   // once; kH4/kH5 re-zero in place

    dim3 eg8((unsigned)(((long long)N_EDGE * 8 + 255) / 256));
    dim3 eg1((unsigned)((N_EDGE + 255) / 256));
    kE12<<<eg8, 256>>>(entity_emb, head, tail, edge_type);
    kE2b<<<eg1, 256>>>(head, edge_type);
    kE3<<<eg1, 256>>>(head);

    dim3 ng16((unsigned)(((long long)N_ENT * 16 + 255) / 256));
    dim3 ug16((unsigned)(((long long)N_USR * 16 + 255) / 256));
    for (int hop = 0; hop < 2; hop++) {
        kH2<<<eg8, 256>>>(head, tail, edge_type, weight);
        kH3<<<eg8, 256>>>(ui_rows, ui_cols, ui_vals);
        kH4<<<ng16, 256>>>(out_ent);
        kH5<<<ug16, 256>>>(latent_emb, out_usr);
    }
}

// round 13
// speedup vs baseline: 2.8734x; 1.4806x over previous
#include <cuda_runtime.h>
#include <math.h>

// Problem constants (match reference)
#define N_ENT   100000
#define N_USR   50000
#define N_EDGE  1000000
#define C       64
#define N_FACT  4
#define NRELM1  9           // N_REL - 1
#define TEMP    0.2f
#define SCALE_R 0.0883883476483184f   // 1 / (2 * sqrt(32))

// ---------------- device scratch (no allocation allowed) ----------------
__device__ __align__(16) float g_ent[N_ENT * C];    // ping
__device__ __align__(16) float g_ent2[N_ENT * C];   // pong
__device__ __align__(16) float g_usr[N_USR * C];
__device__ float g_er[N_EDGE];      // exp(score_r), CSR order
__device__ float g_dt[N_EDGE];      // dot(h,t) -> exp(score_trip), CSR order
__device__ float g_mask[N_EDGE];    // kg_mask, CSR order
__device__ int   g_pack[N_EDGE];    // tail | ((et-1)<<20), CSR order
__device__ int   g_ucol[N_EDGE];    // ui cols, CSR order
__device__ float g_uval[N_EDGE];    // ui vals, CSR order
__device__ int   g_off[N_ENT + 1];
__device__ int   g_uoff[N_USR + 1];
__device__ int   g_deg[N_ENT];
__device__ int   g_cur[N_ENT];
__device__ int   g_udeg[N_USR];
__device__ int   g_ucur[N_USR];
__device__ int   g_bsum[128];
__device__ __align__(16) float g_u_rel[NRELM1 * C];   // (W W^T) w_t
__device__ float g_wnorm2[NRELM1];
__device__ __align__(16) float g_disen_w[N_FACT * C]; // softmax(disen_att) @ weight

// ---------------- tiny dense precompute + cor ----------------
__global__ void k_prep(const float* __restrict__ W,      // kg_W_r [64,64]
                       const float* __restrict__ weight, // [9,64]
                       const float* __restrict__ A,      // disen_weight_att [4,9]
                       float* __restrict__ cor_out) {
    __shared__ float G[64 * 64];
    __shared__ float sm[N_FACT][NRELM1];
    int tid = threadIdx.x;

    // G = W W^T
    for (int idx = tid; idx < 64 * 64; idx += blockDim.x) {
        int i = idx >> 6, j = idx & 63;
        float s = 0.f;
#pragma unroll 8
        for (int c = 0; c < 64; c++) s += W[i * 64 + c] * W[j * 64 + c];
        G[idx] = s;
    }
    __syncthreads();

    // u_t = G @ w_t
    for (int idx = tid; idx < NRELM1 * C; idx += blockDim.x) {
        int t = idx / C, i = idx % C;
        float s = 0.f;
#pragma unroll 8
        for (int j = 0; j < 64; j++) s += G[i * 64 + j] * weight[t * 64 + j];
        g_u_rel[idx] = s;
    }
    if (tid < NRELM1) {
        float s = 0.f;
        for (int c = 0; c < 64; c++) { float v = weight[tid * 64 + c]; s += v * v; }
        g_wnorm2[tid] = s;
    }
    if (tid < N_FACT) {
        float m = -1e30f;
        for (int j = 0; j < NRELM1; j++) m = fmaxf(m, A[tid * NRELM1 + j]);
        float s = 0.f;
        for (int j = 0; j < NRELM1; j++) { float e = expf(A[tid * NRELM1 + j] - m); sm[tid][j] = e; s += e; }
        for (int j = 0; j < NRELM1; j++) sm[tid][j] /= s;
    }
    __syncthreads();

    // disen_w = softmax(A) @ weight
    for (int idx = tid; idx < N_FACT * C; idx += blockDim.x) {
        int f = idx / C, c = idx % C;
        float s = 0.f;
        for (int j = 0; j < NRELM1; j++) s += sm[f][j] * weight[j * 64 + c];
        g_disen_w[idx] = s;
    }

    // cor
    if (tid == 0) {
        float cor = 0.f;
        for (int i = 0; i < NRELM1; i++) {
            float n2 = 0.f;
            for (int f = 0; f < N_FACT; f++) { float v = A[f * NRELM1 + i]; n2 += v * v; }
            float nrm = sqrtf(n2);
            float pos = 0.f;
            for (int f = 0; f < N_FACT; f++) { float v = A[f * NRELM1 + i] / nrm; pos += v * v; }
            float ttl = 0.f;
            for (int j = 0; j < NRELM1; j++) {
                float d = 0.f;
                for (int f = 0; f < N_FACT; f++) d += A[f * NRELM1 + i] * A[f * NRELM1 + j];
                ttl += d;
            }
            cor += (ttl - pos) / TEMP;
        }
        *cor_out = cor;
    }
}

// ---------------- init: copy embeddings to state + output ----------------
__global__ void k_init(const float* __restrict__ eemb, const float* __restrict__ uemb,
                       float* __restrict__ out_ent, float* __restrict__ out_usr) {
    const int NE4 = N_ENT * C / 4, NU4 = N_USR * C / 4;
    int i = blockIdx.x * blockDim.x + threadIdx.x;
    if (i < NE4) {
        float4 v = ((const float4*)eemb)[i];
        ((float4*)g_ent)[i] = v;
        ((float4*)out_ent)[i] = v;
    } else if (i < NE4 + NU4) {
        int j = i - NE4;
        float4 v = ((const float4*)uemb)[j];
        ((float4*)g_usr)[j] = v;
        ((float4*)out_usr)[j] = v;
    }
}

// ---------------- CSR build ----------------
__global__ void k_zero_idx() {
    int i = blockIdx.x * blockDim.x + threadIdx.x;
    if (i < N_ENT) { g_deg[i] = 0; g_cur[i] = 0; }
    if (i < N_USR) { g_udeg[i] = 0; g_ucur[i] = 0; }
}

__global__ void k_hist(const int* __restrict__ keys, int* __restrict__ deg) {
    int i = blockIdx.x * blockDim.x + threadIdx.x;
    if (i < N_EDGE) atomicAdd(&deg[keys[i]], 1);
}

// exclusive scan, pass 1 (blockDim must be 1024)
__global__ void k_scan1(const int* __restrict__ deg, int* __restrict__ off, int n) {
    __shared__ int sm[32];
    int i = blockIdx.x * 1024 + threadIdx.x;
    int v = (i < n) ? deg[i] : 0;
    int lane = threadIdx.x & 31, wid = threadIdx.x >> 5;
    int x = v;
#pragma unroll
    for (int o = 1; o < 32; o <<= 1) {
        int y = __shfl_up_sync(0xffffffffu, x, o);
        if (lane >= o) x += y;
    }
    if (lane == 31) sm[wid] = x;
    __syncthreads();
    if (wid == 0) {
        int s = sm[lane];
#pragma unroll
        for (int o = 1; o < 32; o <<= 1) {
            int y = __shfl_up_sync(0xffffffffu, s, o);
            if (lane >= o) s += y;
        }
        sm[lane] = s;
    }
    __syncthreads();
    int wofs = wid ? sm[wid - 1] : 0;
    if (i < n) off[i] = x - v + wofs;
    if (threadIdx.x == 1023) g_bsum[blockIdx.x] = wofs + x;  // block total
}

__global__ void k_scan2(int nb) {
    if (threadIdx.x == 0) {
        int acc = 0;
        for (int i = 0; i < nb; i++) { int t = g_bsum[i]; g_bsum[i] = acc; acc += t; }
    }
}

__global__ void k_scan3(int* __restrict__ off, int n) {
    int i = blockIdx.x * blockDim.x + threadIdx.x;
    if (i < n) off[i] += g_bsum[i >> 10];
    if (i == 0) off[n] = N_EDGE;
}

__global__ void k_reorder_kg(const int* __restrict__ head, const int* __restrict__ tail,
                             const int* __restrict__ et) {
    int i = blockIdx.x * blockDim.x + threadIdx.x;
    if (i >= N_EDGE) return;
    int h = head[i];
    int p = g_off[h] + atomicAdd(&g_cur[h], 1);
    g_pack[p] = tail[i] | ((et[i] - 1) << 20);
}

__global__ void k_reorder_ui(const int* __restrict__ rows, const int* __restrict__ cols,
                             const float* __restrict__ vals) {
    int i = blockIdx.x * blockDim.x + threadIdx.x;
    if (i >= N_EDGE) return;
    int u = rows[i];
    int p = g_uoff[u] + atomicAdd(&g_ucur[u], 1);
    g_ucol[p] = cols[i];
    g_uval[p] = vals[i];
}

// ---------------- score phase: per-head-segment double softmax, no atomics ----------------
// warp per head entity; lane owns 2 channels (float2)
__global__ void kScore(const float* __restrict__ ent) {
    __shared__ __align__(8) float s_u[NRELM1 * C];
    __shared__ float s_wn[NRELM1];
    for (int i = threadIdx.x; i < NRELM1 * C; i += blockDim.x) s_u[i] = g_u_rel[i];
    if (threadIdx.x < NRELM1) s_wn[threadIdx.x] = g_wnorm2[threadIdx.x];
    __syncthreads();
    int w = blockIdx.x * (blockDim.x >> 5) + (threadIdx.x >> 5);
    int lane = threadIdx.x & 31;
    if (w >= N_ENT) return;
    int beg = g_off[w], end = g_off[w + 1];
    if (beg == end) return;
    float2 hv = *(const float2*)(ent + (size_t)w * C + lane * 2);

    // pass A: score_r (exp'd) + raw dot(h,t), segment sum of exp(score_r)
    float sum_er = 0.f;
    for (int e = beg; e < end; e++) {
        int pk = g_pack[e];
        int tl = pk & 0xFFFFF, t = pk >> 20;
        float2 tv = *(const float2*)(ent + (size_t)tl * C + lane * 2);
        float2 uv = *(const float2*)(s_u + t * C + lane * 2);
        float du = hv.x * uv.x + hv.y * uv.y;
        float dt = hv.x * tv.x + hv.y * tv.y;
#pragma unroll
        for (int o = 16; o; o >>= 1) {
            du += __shfl_xor_sync(0xffffffffu, du, o);
            dt += __shfl_xor_sync(0xffffffffu, dt, o);
        }
        float er = expf(du * SCALE_R);
        sum_er += er;
        if (lane == 0) { g_er[e] = er; g_dt[e] = dt; }
    }
    float inv_r = 1.f / (sum_er + 1e-16f);

    // pass B: score_trip (exp'd), segment sum — edges distributed across lanes
    float sum_est = 0.f;
    for (int e = beg + lane; e < end; e += 32) {
        int t = g_pack[e] >> 20;
        float rs = g_er[e] * inv_r;
        float est = expf(g_dt[e] + rs * rs * s_wn[t]);
        g_dt[e] = est;
        sum_est += est;
    }
#pragma unroll
    for (int o = 16; o; o >>= 1) sum_est += __shfl_xor_sync(0xffffffffu, sum_est, o);
    float inv_t = 1.f / (sum_est + 1e-16f);

    // pass C: kg_mask
    for (int e = beg + lane; e < end; e += 32) g_mask[e] = g_dt[e] * inv_t;
}

// ---------------- hop: entity aggregate + mean + l2norm + residual (fused) ----------------
// warp per entity; gather-style, zero atomics; ping-pong ent buffers
__global__ void kEnt(const float* __restrict__ ent_in, float* __restrict__ ent_out,
                     float* __restrict__ out_ent, const float* __restrict__ weight) {
    __shared__ __align__(8) float s_w[NRELM1 * C];
    for (int i = threadIdx.x; i < NRELM1 * C; i += blockDim.x) s_w[i] = weight[i];
    __syncthreads();
    int n = blockIdx.x * (blockDim.x >> 5) + (threadIdx.x >> 5);
    int lane = threadIdx.x & 31;
    if (n >= N_ENT) return;
    int beg = g_off[n], end = g_off[n + 1];
    float ax = 0.f, ay = 0.f;
    for (int e = beg; e < end; e++) {
        int pk = g_pack[e];
        int tl = pk & 0xFFFFF, t = pk >> 20;
        float m = g_mask[e];
        float2 ev = *(const float2*)(ent_in + (size_t)tl * C + lane * 2);
        float2 wv = *(const float2*)(s_w + t * C + lane * 2);
        ax += ev.x * wv.x * m;
        ay += ev.y * wv.y * m;
    }
    float invc = 1.f / fmaxf((float)(end - beg), 1.f);
    ax *= invc; ay *= invc;
    float ss = ax * ax + ay * ay;
#pragma unroll
    for (int o = 16; o; o >>= 1) ss += __shfl_xor_sync(0xffffffffu, ss, o);
    float inv = 1.f / fmaxf(sqrtf(ss), 1e-12f);
    ax *= inv; ay *= inv;
    *(float2*)(ent_out + (size_t)n * C + lane * 2) = make_float2(ax, ay);
    float2* o2 = (float2*)(out_ent + (size_t)n * C + lane * 2);
    float2 c = *o2; c.x += ax; c.y += ay; *o2 = c;
}

// ---------------- hop: user aggregate + mix + l2norm + residual (fused) ----------------
__global__ void kUsr(const float* __restrict__ ent_in, float* __restrict__ out_usr,
                     const float* __restrict__ latent) {
    __shared__ __align__(8) float s_lat[N_FACT * C];
    __shared__ __align__(8) float s_dw[N_FACT * C];
    for (int i = threadIdx.x; i < N_FACT * C; i += blockDim.x) {
        s_lat[i] = latent[i];
        s_dw[i] = g_disen_w[i];
    }
    __syncthreads();
    int u = blockIdx.x * (blockDim.x >> 5) + (threadIdx.x >> 5);
    int lane = threadIdx.x & 31;
    if (u >= N_USR) return;

    float2 uv = *(const float2*)(g_usr + (size_t)u * C + lane * 2);
    float d[N_FACT];
#pragma unroll
    for (int f = 0; f < N_FACT; f++) {
        const float2 lv = *(const float2*)(s_lat + f * C + lane * 2);
        d[f] = uv.x * lv.x + uv.y * lv.y;
    }
#pragma unroll
    for (int o = 16; o; o >>= 1) {
#pragma unroll
        for (int f = 0; f < N_FACT; f++) d[f] += __shfl_xor_sync(0xffffffffu, d[f], o);
    }
    float m = fmaxf(fmaxf(d[0], d[1]), fmaxf(d[2], d[3]));
    float e[N_FACT], s = 0.f;
#pragma unroll
    for (int f = 0; f < N_FACT; f++) { e[f] = expf(d[f] - m); s += e[f]; }
    float mx = 0.f, my = 0.f;
#pragma unroll
    for (int f = 0; f < N_FACT; f++) {
        float sc = e[f] / s;
        const float2 dv = *(const float2*)(s_dw + f * C + lane * 2);
        mx += sc * dv.x; my += sc * dv.y;
    }

    int beg = g_uoff[u], end = g_uoff[u + 1];
    float ax = 0.f, ay = 0.f;
    for (int ee = beg; ee < end; ee++) {
        int cl = g_ucol[ee];
        float v = g_uval[ee];
        float2 ev = *(const float2*)(ent_in + (size_t)cl * C + lane * 2);
        ax += ev.x * v;
        ay += ev.y * v;
    }
    float rx = ax * (1.f + mx), ry = ay * (1.f + my);
    float ss = rx * rx + ry * ry;
#pragma unroll
    for (int o = 16; o; o >>= 1) ss += __shfl_xor_sync(0xffffffffu, ss, o);
    float inv = 1.f / fmaxf(sqrtf(ss), 1e-12f);
    rx *= inv; ry *= inv;
    *(float2*)(g_usr + (size_t)u * C + lane * 2) = make_float2(rx, ry);
    float2* o2 = (float2*)(out_usr + (size_t)u * C + lane * 2);
    float2 c = *o2; c.x += rx; c.y += ry; *o2 = c;
}

// ---------------- launch ----------------
extern "C" void kernel_launch(void* const* d_in, const int* in_sizes, int n_in,
                              void* d_out, int out_size) {
    const float* user_emb   = (const float*)d_in[0];
    const float* entity_emb = (const float*)d_in[1];
    const float* latent_emb = (const float*)d_in[2];
    const float* weight     = (const float*)d_in[3];
    const float* disen      = (const float*)d_in[4];
    const float* kgW        = (const float*)d_in[5];
    const float* ui_vals    = (const float*)d_in[6];
    const int*   edge_index = (const int*)d_in[7];
    const int*   edge_type  = (const int*)d_in[8];
    const int*   ui_rows    = (const int*)d_in[9];
    const int*   ui_cols    = (const int*)d_in[10];

    float* out     = (float*)d_out;
    float* out_ent = out;
    float* out_usr = out + (size_t)N_ENT * C;
    float* out_cor = out + (size_t)N_ENT * C + (size_t)N_USR * C;

    const int* head = edge_index;
    const int* tail = edge_index + N_EDGE;

    // device-global addresses (pure lookups; graph-capture safe)
    void *p_deg, *p_off, *p_udeg, *p_uoff, *p_ent, *p_ent2;
    cudaGetSymbolAddress(&p_deg, g_deg);
    cudaGetSymbolAddress(&p_off, g_off);
    cudaGetSymbolAddress(&p_udeg, g_udeg);
    cudaGetSymbolAddress(&p_uoff, g_uoff);
    cudaGetSymbolAddress(&p_ent, g_ent);
    cudaGetSymbolAddress(&p_ent2, g_ent2);

    k_prep<<<1, 256>>>(kgW, weight, disen, out_cor);

    int nInit = (N_ENT * C / 4 + N_USR * C / 4 + 255) / 256;
    k_init<<<nInit, 256>>>(entity_emb, user_emb, out_ent, out_usr);
    k_zero_idx<<<(N_ENT + 255) / 256, 256>>>();

    const int egE = (N_EDGE + 255) / 256;
    k_hist<<<egE, 256>>>(head, (int*)p_deg);
    k_hist<<<egE, 256>>>(ui_rows, (int*)p_udeg);

    // scan entity degrees -> g_off
    k_scan1<<<(N_ENT + 1023) / 1024, 1024>>>((const int*)p_deg, (int*)p_off, N_ENT);
    k_scan2<<<1, 32>>>((N_ENT + 1023) / 1024);
    k_scan3<<<(N_ENT + 255) / 256, 256>>>((int*)p_off, N_ENT);
    // scan user degrees -> g_uoff
    k_scan1<<<(N_USR + 1023) / 1024, 1024>>>((const int*)p_udeg, (int*)p_uoff, N_USR);
    k_scan2<<<1, 32>>>((N_USR + 1023) / 1024);
    k_scan3<<<(N_USR + 255) / 256, 256>>>((int*)p_uoff, N_USR);

    k_reorder_kg<<<egE, 256>>>(head, tail, edge_type);
    k_reorder_ui<<<egE, 256>>>(ui_rows, ui_cols, ui_vals);

    const int WPB = 8;  // warps per block (256 threads)
    kScore<<<(N_ENT + WPB - 1) / WPB, 256>>>(entity_emb);

    // hop 1: both aggregations read g_ent (old); entity update writes g_ent2
    kUsr<<<(N_USR + WPB - 1) / WPB, 256>>>((const float*)p_ent, out_usr, latent_emb);
    kEnt<<<(N_ENT + WPB - 1) / WPB, 256>>>((const float*)p_ent, (float*)p_ent2, out_ent, weight);
    // hop 2: read g_ent2, write g_ent
    kUsr<<<(N_USR + WPB - 1) / WPB, 256>>>((const float*)p_ent2, out_usr, latent_emb);
    kEnt<<<(N_ENT + WPB - 1) / WPB, 256>>>((const float*)p_ent2, (float*)p_ent, out_ent, weight);
}

// round 14
// speedup vs baseline: 3.2370x; 1.1266x over previous
#include <cuda_runtime.h>
#include <math.h>

// Problem constants (match reference)
#define N_ENT   100000
#define N_USR   50000
#define N_EDGE  1000000
#define C       64
#define N_FACT  4
#define NRELM1  9           // N_REL - 1
#define TEMP    0.2f
#define SCALE_R 0.0883883476483184f   // 1 / (2 * sqrt(32))

#define WPB        8                  // warps per block
#define ROWS_PER_BLK (WPB * 2)        // 16 rows (2 per warp, 16 lanes each)
#define ENT_BLOCKS ((N_ENT + ROWS_PER_BLK - 1) / ROWS_PER_BLK)
#define USR_BLOCKS ((N_USR + ROWS_PER_BLK - 1) / ROWS_PER_BLK)

// ---------------- device scratch (no allocation allowed) ----------------
__device__ __align__(16) float g_ent[N_ENT * C];    // ping
__device__ __align__(16) float g_ent2[N_ENT * C];   // pong
__device__ __align__(16) float g_usr[N_USR * C];
__device__ float g_er[N_EDGE];      // exp(score_r), CSR order
__device__ float g_dt[N_EDGE];      // dot(h,t) -> exp(score_trip), CSR order
__device__ float g_mask[N_EDGE];    // kg_mask, CSR order
__device__ int   g_pack[N_EDGE];    // tail | ((et-1)<<20), CSR order
__device__ int   g_ucol[N_EDGE];    // ui cols, CSR order
__device__ float g_uval[N_EDGE];    // ui vals, CSR order
__device__ int   g_off[N_ENT + 1];
__device__ int   g_uoff[N_USR + 1];
__device__ int   g_deg[N_ENT];
__device__ int   g_cur[N_ENT];
__device__ int   g_udeg[N_USR];
__device__ int   g_ucur[N_USR];
__device__ int   g_bsum[128];
__device__ __align__(16) float g_u_rel[NRELM1 * C];   // (W W^T) w_t
__device__ float g_wnorm2[NRELM1];
__device__ __align__(16) float g_disen_w[N_FACT * C]; // softmax(disen_att) @ weight

__device__ __forceinline__ float dot4(float4 a, float4 b) {
    return a.x * b.x + a.y * b.y + a.z * b.z + a.w * b.w;
}

// ---------------- tiny dense precompute + cor ----------------
__global__ void k_prep(const float* __restrict__ W,      // kg_W_r [64,64]
                       const float* __restrict__ weight, // [9,64]
                       const float* __restrict__ A,      // disen_weight_att [4,9]
                       float* __restrict__ cor_out) {
    __shared__ float G[64 * 64];
    __shared__ float sm[N_FACT][NRELM1];
    int tid = threadIdx.x;

    for (int idx = tid; idx < 64 * 64; idx += blockDim.x) {
        int i = idx >> 6, j = idx & 63;
        float s = 0.f;
#pragma unroll 8
        for (int c = 0; c < 64; c++) s += W[i * 64 + c] * W[j * 64 + c];
        G[idx] = s;
    }
    __syncthreads();

    for (int idx = tid; idx < NRELM1 * C; idx += blockDim.x) {
        int t = idx / C, i = idx % C;
        float s = 0.f;
#pragma unroll 8
        for (int j = 0; j < 64; j++) s += G[i * 64 + j] * weight[t * 64 + j];
        g_u_rel[idx] = s;
    }
    if (tid < NRELM1) {
        float s = 0.f;
        for (int c = 0; c < 64; c++) { float v = weight[tid * 64 + c]; s += v * v; }
        g_wnorm2[tid] = s;
    }
    if (tid < N_FACT) {
        float m = -1e30f;
        for (int j = 0; j < NRELM1; j++) m = fmaxf(m, A[tid * NRELM1 + j]);
        float s = 0.f;
        for (int j = 0; j < NRELM1; j++) { float e = expf(A[tid * NRELM1 + j] - m); sm[tid][j] = e; s += e; }
        for (int j = 0; j < NRELM1; j++) sm[tid][j] /= s;
    }
    __syncthreads();

    for (int idx = tid; idx < N_FACT * C; idx += blockDim.x) {
        int f = idx / C, c = idx % C;
        float s = 0.f;
        for (int j = 0; j < NRELM1; j++) s += sm[f][j] * weight[j * 64 + c];
        g_disen_w[idx] = s;
    }

    if (tid == 0) {
        float cor = 0.f;
        for (int i = 0; i < NRELM1; i++) {
            float n2 = 0.f;
            for (int f = 0; f < N_FACT; f++) { float v = A[f * NRELM1 + i]; n2 += v * v; }
            float nrm = sqrtf(n2);
            float pos = 0.f;
            for (int f = 0; f < N_FACT; f++) { float v = A[f * NRELM1 + i] / nrm; pos += v * v; }
            float ttl = 0.f;
            for (int j = 0; j < NRELM1; j++) {
                float d = 0.f;
                for (int f = 0; f < N_FACT; f++) d += A[f * NRELM1 + i] * A[f * NRELM1 + j];
                ttl += d;
            }
            cor += (ttl - pos) / TEMP;
        }
        *cor_out = cor;
    }
}

// ---------------- init: copy embeddings to state + output ----------------
__global__ void k_init(const float* __restrict__ eemb, const float* __restrict__ uemb,
                       float* __restrict__ out_ent, float* __restrict__ out_usr) {
    const int NE4 = N_ENT * C / 4, NU4 = N_USR * C / 4;
    int i = blockIdx.x * blockDim.x + threadIdx.x;
    if (i < NE4) {
        float4 v = ((const float4*)eemb)[i];
        ((float4*)g_ent)[i] = v;
        ((float4*)out_ent)[i] = v;
    } else if (i < NE4 + NU4) {
        int j = i - NE4;
        float4 v = ((const float4*)uemb)[j];
        ((float4*)g_usr)[j] = v;
        ((float4*)out_usr)[j] = v;
    }
}

// ---------------- CSR build ----------------
__global__ void k_zero_idx() {
    int i = blockIdx.x * blockDim.x + threadIdx.x;
    if (i < N_ENT) { g_deg[i] = 0; g_cur[i] = 0; }
    if (i < N_USR) { g_udeg[i] = 0; g_ucur[i] = 0; }
}

__global__ void k_hist(const int* __restrict__ keys, int* __restrict__ deg) {
    int i = blockIdx.x * blockDim.x + threadIdx.x;
    if (i < N_EDGE) atomicAdd(&deg[keys[i]], 1);
}

// exclusive scan, pass 1 (blockDim must be 1024)
__global__ void k_scan1(const int* __restrict__ deg, int* __restrict__ off, int n) {
    __shared__ int sm[32];
    int i = blockIdx.x * 1024 + threadIdx.x;
    int v = (i < n) ? deg[i] : 0;
    int lane = threadIdx.x & 31, wid = threadIdx.x >> 5;
    int x = v;
#pragma unroll
    for (int o = 1; o < 32; o <<= 1) {
        int y = __shfl_up_sync(0xffffffffu, x, o);
        if (lane >= o) x += y;
    }
    if (lane == 31) sm[wid] = x;
    __syncthreads();
    if (wid == 0) {
        int s = sm[lane];
#pragma unroll
        for (int o = 1; o < 32; o <<= 1) {
            int y = __shfl_up_sync(0xffffffffu, s, o);
            if (lane >= o) s += y;
        }
        sm[lane] = s;
    }
    __syncthreads();
    int wofs = wid ? sm[wid - 1] : 0;
    if (i < n) off[i] = x - v + wofs;
    if (threadIdx.x == 1023) g_bsum[blockIdx.x] = wofs + x;
}

__global__ void k_scan2(int nb) {
    if (threadIdx.x == 0) {
        int acc = 0;
        for (int i = 0; i < nb; i++) { int t = g_bsum[i]; g_bsum[i] = acc; acc += t; }
    }
}

__global__ void k_scan3(int* __restrict__ off, int n) {
    int i = blockIdx.x * blockDim.x + threadIdx.x;
    if (i < n) off[i] += g_bsum[i >> 10];
    if (i == 0) off[n] = N_EDGE;
}

__global__ void k_reorder_kg(const int* __restrict__ head, const int* __restrict__ tail,
                             const int* __restrict__ et) {
    int i = blockIdx.x * blockDim.x + threadIdx.x;
    if (i >= N_EDGE) return;
    int h = head[i];
    int p = g_off[h] + atomicAdd(&g_cur[h], 1);
    g_pack[p] = tail[i] | ((et[i] - 1) << 20);
}

__global__ void k_reorder_ui(const int* __restrict__ rows, const int* __restrict__ cols,
                             const float* __restrict__ vals) {
    int i = blockIdx.x * blockDim.x + threadIdx.x;
    if (i >= N_EDGE) return;
    int u = rows[i];
    int p = g_uoff[u] + atomicAdd(&g_ucur[u], 1);
    g_ucol[p] = cols[i];
    g_uval[p] = vals[i];
}

// ---------------- score phase: 8 lanes/edge, 4 edges in flight per warp ----------------
__global__ void kScore(const float* __restrict__ ent) {
    __shared__ __align__(16) float s_u[NRELM1 * C];
    __shared__ float s_wn[NRELM1];
    for (int i = threadIdx.x; i < NRELM1 * C; i += blockDim.x) s_u[i] = g_u_rel[i];
    if (threadIdx.x < NRELM1) s_wn[threadIdx.x] = g_wnorm2[threadIdx.x];
    __syncthreads();
    int w = blockIdx.x * (blockDim.x >> 5) + (threadIdx.x >> 5);
    int lane = threadIdx.x & 31;
    if (w >= N_ENT) return;
    int beg = g_off[w], end = g_off[w + 1];
    if (beg == end) return;
    int sub = lane >> 3;      // edge slot 0..3
    int cl  = lane & 7;       // channel group: owns channels cl*8..cl*8+7

    const float4* hp = (const float4*)(ent + (size_t)w * C + cl * 8);
    float4 h0 = hp[0], h1 = hp[1];

    // pass A: 4 edges concurrently; 8-lane dot reduction
    float sum_er = 0.f;
    for (int e0 = beg; e0 < end; e0 += 4) {
        int e = e0 + sub;
        bool valid = (e < end);
        int pk = valid ? g_pack[e] : 0;
        int tl = pk & 0xFFFFF, t = pk >> 20;
        const float4* tp = (const float4*)(ent + (size_t)tl * C + cl * 8);
        const float4* up = (const float4*)(s_u + t * C + cl * 8);
        float4 t0 = tp[0], t1 = tp[1];
        float4 u0 = up[0], u1 = up[1];
        float du = dot4(h0, u0) + dot4(h1, u1);
        float dt = dot4(h0, t0) + dot4(h1, t1);
#pragma unroll
        for (int o = 4; o; o >>= 1) {
            du += __shfl_xor_sync(0xffffffffu, du, o);
            dt += __shfl_xor_sync(0xffffffffu, dt, o);
        }
        if (valid && cl == 0) {
            float er = expf(du * SCALE_R);
            g_er[e] = er;
            g_dt[e] = dt;
            sum_er += er;
        }
    }
#pragma unroll
    for (int o = 16; o; o >>= 1) sum_er += __shfl_xor_sync(0xffffffffu, sum_er, o);
    float inv_r = 1.f / (sum_er + 1e-16f);

    // pass B: score_trip (exp'd), lane-strided
    float sum_est = 0.f;
    for (int e = beg + lane; e < end; e += 32) {
        int t = g_pack[e] >> 20;
        float rs = g_er[e] * inv_r;
        float est = expf(g_dt[e] + rs * rs * s_wn[t]);
        g_dt[e] = est;
        sum_est += est;
    }
#pragma unroll
    for (int o = 16; o; o >>= 1) sum_est += __shfl_xor_sync(0xffffffffu, sum_est, o);
    float inv_t = 1.f / (sum_est + 1e-16f);

    // pass C: kg_mask
    for (int e = beg + lane; e < end; e += 32) g_mask[e] = g_dt[e] * inv_t;
}

// ---------------- merged hop kernel: entity blocks then user blocks ----------------
// 16 lanes per row (float4/lane), 2 rows per warp, unroll-2 edge loops
__global__ void kHop(const float* __restrict__ ent_in, float* __restrict__ ent_out,
                     float* __restrict__ out_ent, float* __restrict__ out_usr,
                     const float* __restrict__ weight, const float* __restrict__ latent) {
    __shared__ __align__(16) float s_w[NRELM1 * C];
    __shared__ __align__(16) float s_lat[N_FACT * C];
    __shared__ __align__(16) float s_dw[N_FACT * C];
    bool is_ent = (blockIdx.x < ENT_BLOCKS);
    if (is_ent) {
        for (int i = threadIdx.x; i < NRELM1 * C; i += blockDim.x) s_w[i] = weight[i];
    } else {
        for (int i = threadIdx.x; i < N_FACT * C; i += blockDim.x) {
            s_lat[i] = latent[i];
            s_dw[i] = g_disen_w[i];
        }
    }
    __syncthreads();

    int warp = threadIdx.x >> 5;
    int lane = threadIdx.x & 31;
    int half = lane >> 4;     // row within warp
    int sl   = lane & 15;     // lane within row; owns channels sl*4..sl*4+3

    if (is_ent) {
        int n = blockIdx.x * ROWS_PER_BLK + warp * 2 + half;
        if (n >= N_ENT) return;
        int beg = g_off[n], end = g_off[n + 1];
        float4 acc = make_float4(0.f, 0.f, 0.f, 0.f);
        int e = beg;
        for (; e + 1 < end; e += 2) {
            int pk0 = g_pack[e], pk1 = g_pack[e + 1];
            float m0 = g_mask[e], m1 = g_mask[e + 1];
            float4 ev0 = ((const float4*)(ent_in + (size_t)(pk0 & 0xFFFFF) * C))[sl];
            float4 ev1 = ((const float4*)(ent_in + (size_t)(pk1 & 0xFFFFF) * C))[sl];
            float4 wv0 = ((const float4*)(s_w + (pk0 >> 20) * C))[sl];
            float4 wv1 = ((const float4*)(s_w + (pk1 >> 20) * C))[sl];
            acc.x += ev0.x * wv0.x * m0 + ev1.x * wv1.x * m1;
            acc.y += ev0.y * wv0.y * m0 + ev1.y * wv1.y * m1;
            acc.z += ev0.z * wv0.z * m0 + ev1.z * wv1.z * m1;
            acc.w += ev0.w * wv0.w * m0 + ev1.w * wv1.w * m1;
        }
        if (e < end) {
            int pk = g_pack[e];
            float m = g_mask[e];
            float4 ev = ((const float4*)(ent_in + (size_t)(pk & 0xFFFFF) * C))[sl];
            float4 wv = ((const float4*)(s_w + (pk >> 20) * C))[sl];
            acc.x += ev.x * wv.x * m; acc.y += ev.y * wv.y * m;
            acc.z += ev.z * wv.z * m; acc.w += ev.w * wv.w * m;
        }
        float invc = 1.f / fmaxf((float)(end - beg), 1.f);
        acc.x *= invc; acc.y *= invc; acc.z *= invc; acc.w *= invc;
        float ss = dot4(acc, acc);
#pragma unroll
        for (int o = 8; o; o >>= 1) ss += __shfl_xor_sync(0xffffffffu, ss, o);
        float inv = 1.f / fmaxf(sqrtf(ss), 1e-12f);
        acc.x *= inv; acc.y *= inv; acc.z *= inv; acc.w *= inv;
        ((float4*)(ent_out + (size_t)n * C))[sl] = acc;
        float4* o4 = (float4*)(out_ent + (size_t)n * C) + sl;
        float4 c = *o4;
        c.x += acc.x; c.y += acc.y; c.z += acc.z; c.w += acc.w;
        *o4 = c;
    } else {
        int u = (blockIdx.x - ENT_BLOCKS) * ROWS_PER_BLK + warp * 2 + half;
        if (u >= N_USR) return;

        float4 uv = ((const float4*)(g_usr + (size_t)u * C))[sl];
        float d[N_FACT];
#pragma unroll
        for (int f = 0; f < N_FACT; f++)
            d[f] = dot4(uv, ((const float4*)(s_lat + f * C))[sl]);
#pragma unroll
        for (int o = 8; o; o >>= 1) {
#pragma unroll
            for (int f = 0; f < N_FACT; f++) d[f] += __shfl_xor_sync(0xffffffffu, d[f], o);
        }
        float m = fmaxf(fmaxf(d[0], d[1]), fmaxf(d[2], d[3]));
        float e0 = expf(d[0] - m), e1 = expf(d[1] - m), e2 = expf(d[2] - m), e3 = expf(d[3] - m);
        float s = e0 + e1 + e2 + e3;
        float4 mix = make_float4(0.f, 0.f, 0.f, 0.f);
        float sc[N_FACT] = {e0 / s, e1 / s, e2 / s, e3 / s};
#pragma unroll
        for (int f = 0; f < N_FACT; f++) {
            float4 dv = ((const float4*)(s_dw + f * C))[sl];
            mix.x += sc[f] * dv.x; mix.y += sc[f] * dv.y;
            mix.z += sc[f] * dv.z; mix.w += sc[f] * dv.w;
        }

        int beg = g_uoff[u], end = g_uoff[u + 1];
        float4 acc = make_float4(0.f, 0.f, 0.f, 0.f);
        int e = beg;
        for (; e + 1 < end; e += 2) {
            int c0 = g_ucol[e], c1 = g_ucol[e + 1];
            float v0 = g_uval[e], v1 = g_uval[e + 1];
            float4 a0 = ((const float4*)(ent_in + (size_t)c0 * C))[sl];
            float4 a1 = ((const float4*)(ent_in + (size_t)c1 * C))[sl];
            acc.x += a0.x * v0 + a1.x * v1;
            acc.y += a0.y * v0 + a1.y * v1;
            acc.z += a0.z * v0 + a1.z * v1;
            acc.w += a0.w * v0 + a1.w * v1;
        }
        if (e < end) {
            int cc = g_ucol[e];
            float v = g_uval[e];
            float4 a0 = ((const float4*)(ent_in + (size_t)cc * C))[sl];
            acc.x += a0.x * v; acc.y += a0.y * v; acc.z += a0.z * v; acc.w += a0.w * v;
        }
        float4 r = make_float4(acc.x * (1.f + mix.x), acc.y * (1.f + mix.y),
                               acc.z * (1.f + mix.z), acc.w * (1.f + mix.w));
        float ss = dot4(r, r);
#pragma unroll
        for (int o = 8; o; o >>= 1) ss += __shfl_xor_sync(0xffffffffu, ss, o);
        float inv = 1.f / fmaxf(sqrtf(ss), 1e-12f);
        r.x *= inv; r.y *= inv; r.z *= inv; r.w *= inv;
        ((float4*)(g_usr + (size_t)u * C))[sl] = r;
        float4* o4 = (float4*)(out_usr + (size_t)u * C) + sl;
        float4 c = *o4;
        c.x += r.x; c.y += r.y; c.z += r.z; c.w += r.w;
        *o4 = c;
    }
}

// ---------------- launch ----------------
extern "C" void kernel_launch(void* const* d_in, const int* in_sizes, int n_in,
                              void* d_out, int out_size) {
    const float* user_emb   = (const float*)d_in[0];
    const float* entity_emb = (const float*)d_in[1];
    const float* latent_emb = (const float*)d_in[2];
    const float* weight     = (const float*)d_in[3];
    const float* disen      = (const float*)d_in[4];
    const float* kgW        = (const float*)d_in[5];
    const float* ui_vals    = (const float*)d_in[6];
    const int*   edge_index = (const int*)d_in[7];
    const int*   edge_type  = (const int*)d_in[8];
    const int*   ui_rows    = (const int*)d_in[9];
    const int*   ui_cols    = (const int*)d_in[10];

    float* out     = (float*)d_out;
    float* out_ent = out;
    float* out_usr = out + (size_t)N_ENT * C;
    float* out_cor = out + (size_t)N_ENT * C + (size_t)N_USR * C;

    const int* head = edge_index;
    const int* tail = edge_index + N_EDGE;

    void *p_deg, *p_off, *p_udeg, *p_uoff, *p_ent, *p_ent2;
    cudaGetSymbolAddress(&p_deg, g_deg);
    cudaGetSymbolAddress(&p_off, g_off);
    cudaGetSymbolAddress(&p_udeg, g_udeg);
    cudaGetSymbolAddress(&p_uoff, g_uoff);
    cudaGetSymbolAddress(&p_ent, g_ent);
    cudaGetSymbolAddress(&p_ent2, g_ent2);

    k_prep<<<1, 256>>>(kgW, weight, disen, out_cor);

    int nInit = (N_ENT * C / 4 + N_USR * C / 4 + 255) / 256;
    k_init<<<nInit, 256>>>(entity_emb, user_emb, out_ent, out_usr);
    k_zero_idx<<<(N_ENT + 255) / 256, 256>>>();

    const int egE = (N_EDGE + 255) / 256;
    k_hist<<<egE, 256>>>(head, (int*)p_deg);
    k_hist<<<egE, 256>>>(ui_rows, (int*)p_udeg);

    k_scan1<<<(N_ENT + 1023) / 1024, 1024>>>((const int*)p_deg, (int*)p_off, N_ENT);
    k_scan2<<<1, 32>>>((N_ENT + 1023) / 1024);
    k_scan3<<<(N_ENT + 255) / 256, 256>>>((int*)p_off, N_ENT);
    k_scan1<<<(N_USR + 1023) / 1024, 1024>>>((const int*)p_udeg, (int*)p_uoff, N_USR);
    k_scan2<<<1, 32>>>((N_USR + 1023) / 1024);
    k_scan3<<<(N_USR + 255) / 256, 256>>>((int*)p_uoff, N_USR);

    k_reorder_kg<<<egE, 256>>>(head, tail, edge_type);
    k_reorder_ui<<<egE, 256>>>(ui_rows, ui_cols, ui_vals);

    kScore<<<(N_ENT + WPB - 1) / WPB, 256>>>(entity_emb);

    const int hopGrid = ENT_BLOCKS + USR_BLOCKS;
    // hop 1: both paths read g_ent; entity path writes g_ent2
    kHop<<<hopGrid, 256>>>((const float*)p_ent, (float*)p_ent2, out_ent, out_usr,
                           weight, latent_emb);
    // hop 2: read g_ent2, write g_ent
    kHop<<<hopGrid, 256>>>((const float*)p_ent2, (float*)p_ent, out_ent, out_usr,
                           weight, latent_emb);
}

// round 15
// speedup vs baseline: 3.3246x; 1.0270x over previous
#include <cuda_runtime.h>
#include <math.h>

// Problem constants (match reference)
#define N_ENT   100000
#define N_USR   50000
#define N_EDGE  1000000
#define C       64
#define N_FACT  4
#define NRELM1  9           // N_REL - 1
#define TEMP    0.2f
#define SCALE_R 0.0883883476483184f   // 1 / (2 * sqrt(32))

#define WPB        8                  // warps per block
#define SCORE_BLOCKS ((N_ENT + WPB - 1) / WPB)
#define ROWS_PER_BLK (WPB * 2)        // 16 rows (2 per warp, 16 lanes each)
#define ENT_BLOCKS ((N_ENT + ROWS_PER_BLK - 1) / ROWS_PER_BLK)
#define USR_BLOCKS ((N_USR + ROWS_PER_BLK - 1) / ROWS_PER_BLK)

#define NB_E ((N_ENT + 1023) / 1024)
#define NB_U ((N_USR + 1023) / 1024)

// ---------------- device scratch (no allocation allowed) ----------------
__device__ __align__(16) float g_ent[N_ENT * C];    // ping
__device__ __align__(16) float g_ent2[N_ENT * C];   // pong
__device__ __align__(16) float g_usr[N_USR * C];
__device__ float g_er[N_EDGE];      // exp(score_r), CSR order
__device__ float g_dt[N_EDGE];      // dot(h,t) -> exp(score_trip), CSR order
__device__ int   g_pack[N_EDGE];    // tail | ((et-1)<<20), CSR order
__device__ __align__(16) int2 g_epack[N_EDGE];  // {pack, mask bits}, CSR order
__device__ __align__(16) int2 g_upack[N_EDGE];  // {ucol, uval bits}, CSR order
__device__ int   g_off[N_ENT + 1];
__device__ int   g_uoff[N_USR + 1];
__device__ int   g_deg[N_ENT];
__device__ int   g_cur[N_ENT];
__device__ int   g_udeg[N_USR];
__device__ int   g_ucur[N_USR];
__device__ int   g_bsum[128];
__device__ int   g_ubsum[128];
__device__ __align__(16) float g_u_rel[NRELM1 * C];   // (W W^T) w_t
__device__ float g_wnorm2[NRELM1];
__device__ __align__(16) float g_disen_w[N_FACT * C]; // softmax(disen_att) @ weight

__device__ __forceinline__ float dot4(float4 a, float4 b) {
    return a.x * b.x + a.y * b.y + a.z * b.z + a.w * b.w;
}

// ---------------- tiny dense precompute + cor ----------------
__global__ void k_prep(const float* __restrict__ W,      // kg_W_r [64,64]
                       const float* __restrict__ weight, // [9,64]
                       const float* __restrict__ A,      // disen_weight_att [4,9]
                       float* __restrict__ cor_out) {
    __shared__ float G[64 * 64];
    __shared__ float sm[N_FACT][NRELM1];
    int tid = threadIdx.x;

    for (int idx = tid; idx < 64 * 64; idx += blockDim.x) {
        int i = idx >> 6, j = idx & 63;
        float s = 0.f;
#pragma unroll 8
        for (int c = 0; c < 64; c++) s += W[i * 64 + c] * W[j * 64 + c];
        G[idx] = s;
    }
    __syncthreads();

    for (int idx = tid; idx < NRELM1 * C; idx += blockDim.x) {
        int t = idx / C, i = idx % C;
        float s = 0.f;
#pragma unroll 8
        for (int j = 0; j < 64; j++) s += G[i * 64 + j] * weight[t * 64 + j];
        g_u_rel[idx] = s;
    }
    if (tid < NRELM1) {
        float s = 0.f;
        for (int c = 0; c < 64; c++) { float v = weight[tid * 64 + c]; s += v * v; }
        g_wnorm2[tid] = s;
    }
    if (tid < N_FACT) {
        float m = -1e30f;
        for (int j = 0; j < NRELM1; j++) m = fmaxf(m, A[tid * NRELM1 + j]);
        float s = 0.f;
        for (int j = 0; j < NRELM1; j++) { float e = expf(A[tid * NRELM1 + j] - m); sm[tid][j] = e; s += e; }
        for (int j = 0; j < NRELM1; j++) sm[tid][j] /= s;
    }
    __syncthreads();

    for (int idx = tid; idx < N_FACT * C; idx += blockDim.x) {
        int f = idx / C, c = idx % C;
        float s = 0.f;
        for (int j = 0; j < NRELM1; j++) s += sm[f][j] * weight[j * 64 + c];
        g_disen_w[idx] = s;
    }

    if (tid == 0) {
        float cor = 0.f;
        for (int i = 0; i < NRELM1; i++) {
            float n2 = 0.f;
            for (int f = 0; f < N_FACT; f++) { float v = A[f * NRELM1 + i]; n2 += v * v; }
            float nrm = sqrtf(n2);
            float pos = 0.f;
            for (int f = 0; f < N_FACT; f++) { float v = A[f * NRELM1 + i] / nrm; pos += v * v; }
            float ttl = 0.f;
            for (int j = 0; j < NRELM1; j++) {
                float d = 0.f;
                for (int f = 0; f < N_FACT; f++) d += A[f * NRELM1 + i] * A[f * NRELM1 + j];
                ttl += d;
            }
            cor += (ttl - pos) / TEMP;
        }
        *cor_out = cor;
    }
}

// ---------------- init: copy embeddings + zero degree arrays ----------------
__global__ void k_init(const float* __restrict__ eemb, const float* __restrict__ uemb,
                       float* __restrict__ out_ent, float* __restrict__ out_usr) {
    const int NE4 = N_ENT * C / 4, NU4 = N_USR * C / 4;
    int i = blockIdx.x * blockDim.x + threadIdx.x;
    if (i < NE4) {
        float4 v = ((const float4*)eemb)[i];
        ((float4*)g_ent)[i] = v;
        ((float4*)out_ent)[i] = v;
    } else if (i < NE4 + NU4) {
        int j = i - NE4;
        float4 v = ((const float4*)uemb)[j];
        ((float4*)g_usr)[j] = v;
        ((float4*)out_usr)[j] = v;
    }
    if (i < N_ENT) { g_deg[i] = 0; g_cur[i] = 0; }
    if (i < N_USR) { g_udeg[i] = 0; g_ucur[i] = 0; }
}

// ---------------- CSR build (merged launches) ----------------
#define EG_E ((N_EDGE + 255) / 256)
__global__ void k_hist2(const int* __restrict__ head, const int* __restrict__ ui_rows) {
    if (blockIdx.x < EG_E) {
        int i = blockIdx.x * blockDim.x + threadIdx.x;
        if (i < N_EDGE) atomicAdd(&g_deg[head[i]], 1);
    } else {
        int i = (blockIdx.x - EG_E) * blockDim.x + threadIdx.x;
        if (i < N_EDGE) atomicAdd(&g_udeg[ui_rows[i]], 1);
    }
}

// exclusive scan pass 1, both arrays in one launch (blockDim = 1024)
__global__ void k_scan1() {
    __shared__ int sm[32];
    bool is_e = (blockIdx.x < NB_E);
    int blk = is_e ? blockIdx.x : blockIdx.x - NB_E;
    int n = is_e ? N_ENT : N_USR;
    const int* deg = is_e ? g_deg : g_udeg;
    int* off = is_e ? g_off : g_uoff;
    int* bsum = is_e ? g_bsum : g_ubsum;
    int i = blk * 1024 + threadIdx.x;
    int v = (i < n) ? deg[i] : 0;
    int lane = threadIdx.x & 31, wid = threadIdx.x >> 5;
    int x = v;
#pragma unroll
    for (int o = 1; o < 32; o <<= 1) {
        int y = __shfl_up_sync(0xffffffffu, x, o);
        if (lane >= o) x += y;
    }
    if (lane == 31) sm[wid] = x;
    __syncthreads();
    if (wid == 0) {
        int s = sm[lane];
#pragma unroll
        for (int o = 1; o < 32; o <<= 1) {
            int y = __shfl_up_sync(0xffffffffu, s, o);
            if (lane >= o) s += y;
        }
        sm[lane] = s;
    }
    __syncthreads();
    int wofs = wid ? sm[wid - 1] : 0;
    if (i < n) off[i] = x - v + wofs;
    if (threadIdx.x == 1023) bsum[blk] = wofs + x;
}

__global__ void k_scan2() {
    if (threadIdx.x == 0) {
        int acc = 0;
        for (int i = 0; i < NB_E; i++) { int t = g_bsum[i]; g_bsum[i] = acc; acc += t; }
    } else if (threadIdx.x == 32) {
        int acc = 0;
        for (int i = 0; i < NB_U; i++) { int t = g_ubsum[i]; g_ubsum[i] = acc; acc += t; }
    }
}

__global__ void k_scan3() {
    int i = blockIdx.x * blockDim.x + threadIdx.x;
    if (i < N_ENT) g_off[i] += g_bsum[i >> 10];
    if (i < N_USR) g_uoff[i] += g_ubsum[i >> 10];
    if (i == 0) { g_off[N_ENT] = N_EDGE; g_uoff[N_USR] = N_EDGE; }
}

__global__ void k_reorder(const int* __restrict__ head, const int* __restrict__ tail,
                          const int* __restrict__ et, const int* __restrict__ rows,
                          const int* __restrict__ cols, const float* __restrict__ vals) {
    if (blockIdx.x < EG_E) {
        int i = blockIdx.x * blockDim.x + threadIdx.x;
        if (i >= N_EDGE) return;
        int h = head[i];
        int p = g_off[h] + atomicAdd(&g_cur[h], 1);
        g_pack[p] = tail[i] | ((et[i] - 1) << 20);
    } else {
        int i = (blockIdx.x - EG_E) * blockDim.x + threadIdx.x;
        if (i >= N_EDGE) return;
        int u = rows[i];
        int p = g_uoff[u] + atomicAdd(&g_ucur[u], 1);
        g_upack[p] = make_int2(cols[i], __float_as_int(vals[i]));
    }
}

// ---------------- user hop body (shared by merged kernels) ----------------
__device__ __forceinline__ void usr_hop_body(int u, int sl,
                                             const float* __restrict__ ent_in,
                                             float* __restrict__ out_usr,
                                             const float* s_lat, const float* s_dw) {
    float4 uv = ((const float4*)(g_usr + (size_t)u * C))[sl];
    float d[N_FACT];
#pragma unroll
    for (int f = 0; f < N_FACT; f++)
        d[f] = dot4(uv, ((const float4*)(s_lat + f * C))[sl]);
#pragma unroll
    for (int o = 8; o; o >>= 1) {
#pragma unroll
        for (int f = 0; f < N_FACT; f++) d[f] += __shfl_xor_sync(0xffffffffu, d[f], o);
    }
    float m = fmaxf(fmaxf(d[0], d[1]), fmaxf(d[2], d[3]));
    float e0 = expf(d[0] - m), e1 = expf(d[1] - m), e2 = expf(d[2] - m), e3 = expf(d[3] - m);
    float s = e0 + e1 + e2 + e3;
    float sc[N_FACT] = {e0 / s, e1 / s, e2 / s, e3 / s};
    float4 mix = make_float4(0.f, 0.f, 0.f, 0.f);
#pragma unroll
    for (int f = 0; f < N_FACT; f++) {
        float4 dv = ((const float4*)(s_dw + f * C))[sl];
        mix.x += sc[f] * dv.x; mix.y += sc[f] * dv.y;
        mix.z += sc[f] * dv.z; mix.w += sc[f] * dv.w;
    }

    int beg = g_uoff[u], end = g_uoff[u + 1];
    float4 acc = make_float4(0.f, 0.f, 0.f, 0.f);
    int e = beg;
    for (; e + 3 < end; e += 4) {
        int2 p0 = g_upack[e],     p1 = g_upack[e + 1];
        int2 p2 = g_upack[e + 2], p3 = g_upack[e + 3];
        float4 a0 = ((const float4*)(ent_in + (size_t)p0.x * C))[sl];
        float4 a1 = ((const float4*)(ent_in + (size_t)p1.x * C))[sl];
        float4 a2 = ((const float4*)(ent_in + (size_t)p2.x * C))[sl];
        float4 a3 = ((const float4*)(ent_in + (size_t)p3.x * C))[sl];
        float v0 = __int_as_float(p0.y), v1 = __int_as_float(p1.y);
        float v2 = __int_as_float(p2.y), v3 = __int_as_float(p3.y);
        acc.x += a0.x * v0 + a1.x * v1 + a2.x * v2 + a3.x * v3;
        acc.y += a0.y * v0 + a1.y * v1 + a2.y * v2 + a3.y * v3;
        acc.z += a0.z * v0 + a1.z * v1 + a2.z * v2 + a3.z * v3;
        acc.w += a0.w * v0 + a1.w * v1 + a2.w * v2 + a3.w * v3;
    }
    for (; e < end; e++) {
        int2 p0 = g_upack[e];
        float4 a0 = ((const float4*)(ent_in + (size_t)p0.x * C))[sl];
        float v = __int_as_float(p0.y);
        acc.x += a0.x * v; acc.y += a0.y * v; acc.z += a0.z * v; acc.w += a0.w * v;
    }
    float4 r = make_float4(acc.x * (1.f + mix.x), acc.y * (1.f + mix.y),
                           acc.z * (1.f + mix.z), acc.w * (1.f + mix.w));
    float ss = dot4(r, r);
#pragma unroll
    for (int o = 8; o; o >>= 1) ss += __shfl_xor_sync(0xffffffffu, ss, o);
    float inv = 1.f / fmaxf(sqrtf(ss), 1e-12f);
    r.x *= inv; r.y *= inv; r.z *= inv; r.w *= inv;
    ((float4*)(g_usr + (size_t)u * C))[sl] = r;
    float4* o4 = (float4*)(out_usr + (size_t)u * C) + sl;
    float4 c = *o4;
    c.x += r.x; c.y += r.y; c.z += r.z; c.w += r.w;
    *o4 = c;
}

// ---------------- merged kernel 1: score (per-head double softmax) + hop1 user ----------
__global__ void kScoreUsr(const float* __restrict__ ent, float* __restrict__ out_usr,
                          const float* __restrict__ latent) {
    __shared__ __align__(16) float s_u[NRELM1 * C];
    __shared__ float s_wn[NRELM1];
    __shared__ __align__(16) float s_lat[N_FACT * C];
    __shared__ __align__(16) float s_dw[N_FACT * C];
    bool is_score = (blockIdx.x < SCORE_BLOCKS);
    if (is_score) {
        for (int i = threadIdx.x; i < NRELM1 * C; i += blockDim.x) s_u[i] = g_u_rel[i];
        if (threadIdx.x < NRELM1) s_wn[threadIdx.x] = g_wnorm2[threadIdx.x];
    } else {
        for (int i = threadIdx.x; i < N_FACT * C; i += blockDim.x) {
            s_lat[i] = latent[i];
            s_dw[i] = g_disen_w[i];
        }
    }
    __syncthreads();
    int lane = threadIdx.x & 31;

    if (!is_score) {
        int warp = threadIdx.x >> 5;
        int u = (blockIdx.x - SCORE_BLOCKS) * ROWS_PER_BLK + warp * 2 + (lane >> 4);
        if (u >= N_USR) return;
        usr_hop_body(u, lane & 15, ent, out_usr, s_lat, s_dw);
        return;
    }

    int w = blockIdx.x * WPB + (threadIdx.x >> 5);
    if (w >= N_ENT) return;
    int beg = g_off[w], end = g_off[w + 1];
    if (beg == end) return;
    int sub = lane >> 3;      // edge slot 0..3
    int cl  = lane & 7;       // channel group: owns channels cl*8..cl*8+7

    const float4* hp = (const float4*)(ent + (size_t)w * C + cl * 8);
    float4 h0 = hp[0], h1 = hp[1];

    // pass A: 4 edges concurrently; 8-lane dot reduction
    float sum_er = 0.f;
    for (int e0 = beg; e0 < end; e0 += 4) {
        int e = e0 + sub;
        bool valid = (e < end);
        int pk = valid ? g_pack[e] : 0;
        int tl = pk & 0xFFFFF, t = pk >> 20;
        const float4* tp = (const float4*)(ent + (size_t)tl * C + cl * 8);
        const float4* up = (const float4*)(s_u + t * C + cl * 8);
        float4 t0 = tp[0], t1 = tp[1];
        float4 u0 = up[0], u1 = up[1];
        float du = dot4(h0, u0) + dot4(h1, u1);
        float dt = dot4(h0, t0) + dot4(h1, t1);
#pragma unroll
        for (int o = 4; o; o >>= 1) {
            du += __shfl_xor_sync(0xffffffffu, du, o);
            dt += __shfl_xor_sync(0xffffffffu, dt, o);
        }
        if (valid && cl == 0) {
            float er = expf(du * SCALE_R);
            g_er[e] = er;
            g_dt[e] = dt;
            sum_er += er;
        }
    }
#pragma unroll
    for (int o = 16; o; o >>= 1) sum_er += __shfl_xor_sync(0xffffffffu, sum_er, o);
    float inv_r = 1.f / (sum_er + 1e-16f);

    // pass B: score_trip (exp'd), lane-strided
    float sum_est = 0.f;
    for (int e = beg + lane; e < end; e += 32) {
        int t = g_pack[e] >> 20;
        float rs = g_er[e] * inv_r;
        float est = expf(g_dt[e] + rs * rs * s_wn[t]);
        g_dt[e] = est;
        sum_est += est;
    }
#pragma unroll
    for (int o = 16; o; o >>= 1) sum_est += __shfl_xor_sync(0xffffffffu, sum_est, o);
    float inv_t = 1.f / (sum_est + 1e-16f);

    // pass C: write packed {pack, mask}
    for (int e = beg + lane; e < end; e += 32)
        g_epack[e] = make_int2(g_pack[e], __float_as_int(g_dt[e] * inv_t));
}

// ---------------- entity hop body ----------------
__device__ __forceinline__ void ent_hop_body(int n, int sl,
                                             const float* __restrict__ ent_in,
                                             float* __restrict__ ent_out,
                                             float* __restrict__ out_ent,
                                             const float* s_w) {
    int beg = g_off[n], end = g_off[n + 1];
    float4 acc = make_float4(0.f, 0.f, 0.f, 0.f);
    int e = beg;
    for (; e + 3 < end; e += 4) {
        int2 q0 = g_epack[e],     q1 = g_epack[e + 1];
        int2 q2 = g_epack[e + 2], q3 = g_epack[e + 3];
        float4 ev0 = ((const float4*)(ent_in + (size_t)(q0.x & 0xFFFFF) * C))[sl];
        float4 ev1 = ((const float4*)(ent_in + (size_t)(q1.x & 0xFFFFF) * C))[sl];
        float4 ev2 = ((const float4*)(ent_in + (size_t)(q2.x & 0xFFFFF) * C))[sl];
        float4 ev3 = ((const float4*)(ent_in + (size_t)(q3.x & 0xFFFFF) * C))[sl];
        float4 wv0 = ((const float4*)(s_w + (q0.x >> 20) * C))[sl];
        float4 wv1 = ((const float4*)(s_w + (q1.x >> 20) * C))[sl];
        float4 wv2 = ((const float4*)(s_w + (q2.x >> 20) * C))[sl];
        float4 wv3 = ((const float4*)(s_w + (q3.x >> 20) * C))[sl];
        float m0 = __int_as_float(q0.y), m1 = __int_as_float(q1.y);
        float m2 = __int_as_float(q2.y), m3 = __int_as_float(q3.y);
        acc.x += ev0.x * wv0.x * m0 + ev1.x * wv1.x * m1 + ev2.x * wv2.x * m2 + ev3.x * wv3.x * m3;
        acc.y += ev0.y * wv0.y * m0 + ev1.y * wv1.y * m1 + ev2.y * wv2.y * m2 + ev3.y * wv3.y * m3;
        acc.z += ev0.z * wv0.z * m0 + ev1.z * wv1.z * m1 + ev2.z * wv2.z * m2 + ev3.z * wv3.z * m3;
        acc.w += ev0.w * wv0.w * m0 + ev1.w * wv1.w * m1 + ev2.w * wv2.w * m2 + ev3.w * wv3.w * m3;
    }
    for (; e < end; e++) {
        int2 q = g_epack[e];
        float m = __int_as_float(q.y);
        float4 ev = ((const float4*)(ent_in + (size_t)(q.x & 0xFFFFF) * C))[sl];
        float4 wv = ((const float4*)(s_w + (q.x >> 20) * C))[sl];
        acc.x += ev.x * wv.x * m; acc.y += ev.y * wv.y * m;
        acc.z += ev.z * wv.z * m; acc.w += ev.w * wv.w * m;
    }
    float invc = 1.f / fmaxf((float)(end - beg), 1.f);
    acc.x *= invc; acc.y *= invc; acc.z *= invc; acc.w *= invc;
    float ss = dot4(acc, acc);
#pragma unroll
    for (int o = 8; o; o >>= 1) ss += __shfl_xor_sync(0xffffffffu, ss, o);
    float inv = 1.f / fmaxf(sqrtf(ss), 1e-12f);
    acc.x *= inv; acc.y *= inv; acc.z *= inv; acc.w *= inv;
    ((float4*)(ent_out + (size_t)n * C))[sl] = acc;
    float4* o4 = (float4*)(out_ent + (size_t)n * C) + sl;
    float4 c = *o4;
    c.x += acc.x; c.y += acc.y; c.z += acc.z; c.w += acc.w;
    *o4 = c;
}

// ---------------- hop1 entity only ----------------
__global__ void kEnt1(const float* __restrict__ ent_in, float* __restrict__ ent_out,
                      float* __restrict__ out_ent, const float* __restrict__ weight) {
    __shared__ __align__(16) float s_w[NRELM1 * C];
    for (int i = threadIdx.x; i < NRELM1 * C; i += blockDim.x) s_w[i] = weight[i];
    __syncthreads();
    int warp = threadIdx.x >> 5, lane = threadIdx.x & 31;
    int n = blockIdx.x * ROWS_PER_BLK + warp * 2 + (lane >> 4);
    if (n >= N_ENT) return;
    ent_hop_body(n, lane & 15, ent_in, ent_out, out_ent, s_w);
}

// ---------------- hop2 merged (entity + user) ----------------
__global__ void kHop2(const float* __restrict__ ent_in, float* __restrict__ ent_out,
                      float* __restrict__ out_ent, float* __restrict__ out_usr,
                      const float* __restrict__ weight, const float* __restrict__ latent) {
    __shared__ __align__(16) float s_w[NRELM1 * C];
    __shared__ __align__(16) float s_lat[N_FACT * C];
    __shared__ __align__(16) float s_dw[N_FACT * C];
    bool is_ent = (blockIdx.x < ENT_BLOCKS);
    if (is_ent) {
        for (int i = threadIdx.x; i < NRELM1 * C; i += blockDim.x) s_w[i] = weight[i];
    } else {
        for (int i = threadIdx.x; i < N_FACT * C; i += blockDim.x) {
            s_lat[i] = latent[i];
            s_dw[i] = g_disen_w[i];
        }
    }
    __syncthreads();
    int warp = threadIdx.x >> 5, lane = threadIdx.x & 31;
    int half = lane >> 4, sl = lane & 15;
    if (is_ent) {
        int n = blockIdx.x * ROWS_PER_BLK + warp * 2 + half;
        if (n >= N_ENT) return;
        ent_hop_body(n, sl, ent_in, ent_out, out_ent, s_w);
    } else {
        int u = (blockIdx.x - ENT_BLOCKS) * ROWS_PER_BLK + warp * 2 + half;
        if (u >= N_USR) return;
        usr_hop_body(u, sl, ent_in, out_usr, s_lat, s_dw);
    }
}

// ---------------- launch ----------------
extern "C" void kernel_launch(void* const* d_in, const int* in_sizes, int n_in,
                              void* d_out, int out_size) {
    const float* user_emb   = (const float*)d_in[0];
    const float* entity_emb = (const float*)d_in[1];
    const float* latent_emb = (const float*)d_in[2];
    const float* weight     = (const float*)d_in[3];
    const float* disen      = (const float*)d_in[4];
    const float* kgW        = (const float*)d_in[5];
    const float* ui_vals    = (const float*)d_in[6];
    const int*   edge_index = (const int*)d_in[7];
    const int*   edge_type  = (const int*)d_in[8];
    const int*   ui_rows    = (const int*)d_in[9];
    const int*   ui_cols    = (const int*)d_in[10];

    float* out     = (float*)d_out;
    float* out_ent = out;
    float* out_usr = out + (size_t)N_ENT * C;
    float* out_cor = out + (size_t)N_ENT * C + (size_t)N_USR * C;

    const int* head = edge_index;
    const int* tail = edge_index + N_EDGE;

    void *p_ent, *p_ent2;
    cudaGetSymbolAddress(&p_ent, g_ent);
    cudaGetSymbolAddress(&p_ent2, g_ent2);

    k_prep<<<1, 256>>>(kgW, weight, disen, out_cor);

    int nInit = (N_ENT * C / 4 + N_USR * C / 4 + 255) / 256;
    k_init<<<nInit, 256>>>(entity_emb, user_emb, out_ent, out_usr);

    k_hist2<<<2 * EG_E, 256>>>(head, ui_rows);
    k_scan1<<<NB_E + NB_U, 1024>>>();
    k_scan2<<<1, 64>>>();
    k_scan3<<<(N_ENT + 255) / 256, 256>>>();
    k_reorder<<<2 * EG_E, 256>>>(head, tail, edge_type, ui_rows, ui_cols, ui_vals);

    // score + hop1-user overlapped (hop1-user reads g_ent == entity_emb copy)
    kScoreUsr<<<SCORE_BLOCKS + USR_BLOCKS, 256>>>(entity_emb, out_usr, latent_emb);
    // hop1 entity (needs mask): read g_ent, write g_ent2
    kEnt1<<<ENT_BLOCKS, 256>>>((const float*)p_ent, (float*)p_ent2, out_ent, weight);
    // hop2: read g_ent2, write g_ent
    kHop2<<<ENT_BLOCKS + USR_BLOCKS, 256>>>((const float*)p_ent2, (float*)p_ent,
                                            out_ent, out_usr, weight, latent_emb);
}